// round 7
// baseline (speedup 1.0000x reference)
#include <cuda_runtime.h>
#include <math.h>

static constexpr int NIN   = 8192;   // inner dim for both layers
static constexpr int N_HID = 8192;
static constexpr int N_OUT = 1024;
static constexpr int SB    = 32;     // stats blocks (32*256 = 8192, one elem/thread)
static constexpr int ROW_BLOCKS   = N_HID + N_OUT;        // 9216
static constexpr int TOTAL_BLOCKS = ROW_BLOCKS + SB;      // 9248 (stats at the tail)
static constexpr int FIN_BLOCKS   = 32;

// ---------------- scratch (no allocations allowed) ----------------
__device__ float g_z[NIN];          // layer-1 z = exp(x)
__device__ float g_hidden[N_HID];   // layer-1 output
__device__ float g_w1sum[N_HID];    // W1 row sums
__device__ float g_w2sum[N_OUT];    // W2 row sums

// per-stats-block partials (plain stores; combined deterministically later)
__device__ float              g_psum[SB];
__device__ unsigned int       g_pmin[SB];   // order-preserving key, min
__device__ unsigned long long g_pmax[SB];   // (key<<32)|idx, max => last-argmax

__device__ unsigned int g_ticket = 0;       // reset by the finale's last block

// order-preserving float<->uint key
__device__ __forceinline__ unsigned int fkey(float v) {
    unsigned u = __float_as_uint(v);
    return (u & 0x80000000u) ? ~u : (u | 0x80000000u);
}
__device__ __forceinline__ float fdec(unsigned int k) {
    unsigned u = (k & 0x80000000u) ? (k ^ 0x80000000u) : ~k;
    return __uint_as_float(u);
}

// ---------------------------------------------------------------------------
// ONE streaming wave, zero cross-block sync:
//   bids [0, 8192)        : W1 row sums -> g_w1sum      (pure stream)
//   bids [8192, 9216)     : W2 row sums -> g_w2sum      (pure stream)
//   bids [9216, 9248)     : z = exp(x) + stats partials (ride the idle tail wave)
// ---------------------------------------------------------------------------
__global__ void __launch_bounds__(256) big_kernel(const float* __restrict__ x,
                                                  const float* __restrict__ W1,
                                                  const float* __restrict__ W2)
{
    const int bid = blockIdx.x;
    const int tid = threadIdx.x;

    if (bid >= ROW_BLOCKS) {
        // -------- stats partial block: one element per thread --------
        const int sb = bid - ROW_BLOCKS;
        const int j  = sb * 256 + tid;
        const float v = expf(x[j]);
        g_z[j] = v;

        __shared__ float              ss[256];
        __shared__ unsigned int       smn[256];
        __shared__ unsigned long long smx[256];
        ss[tid]  = v;
        const unsigned k = fkey(v);
        smn[tid] = k;
        smx[tid] = ((unsigned long long)k << 32) | (unsigned)j;
        __syncthreads();
        for (int o = 128; o > 0; o >>= 1) {
            if (tid < o) {
                ss[tid]  += ss[tid + o];
                smn[tid]  = min(smn[tid], smn[tid + o]);
                smx[tid]  = max(smx[tid], smx[tid + o]);
            }
            __syncthreads();
        }
        if (tid == 0) {
            g_psum[sb] = ss[0];
            g_pmin[sb] = smn[0];
            g_pmax[sb] = smx[0];
        }
        return;
    }

    // -------- row-sum block (the proven streaming loop) --------
    const bool isW2 = (bid >= N_HID);
    const float* __restrict__ W = isW2 ? W2 : W1;
    const int  row  = isW2 ? (bid - N_HID) : bid;
    const float4* __restrict__ Wr =
        reinterpret_cast<const float4*>(W + (size_t)row * NIN);

    float acc = 0.f;
    #pragma unroll
    for (int i = 0; i < NIN / 4 / 256; ++i) {
        float4 v = __ldcs(Wr + tid + i * 256);
        acc += (v.x + v.y) + (v.z + v.w);
    }
    #pragma unroll
    for (int o = 16; o > 0; o >>= 1) acc += __shfl_down_sync(0xffffffffu, acc, o);

    __shared__ float swp[8];
    const int wid = tid >> 5, lane = tid & 31;
    if (lane == 0) swp[wid] = acc;
    __syncthreads();

    if (tid == 0) {
        float Wsum = 0.f;
        #pragma unroll
        for (int w = 0; w < 8; ++w) Wsum += swp[w];
        if (isW2) g_w2sum[row] = Wsum; else g_w1sum[row] = Wsum;
    }
}

// ---------------------------------------------------------------------------
// Finale (grid 32 x 256):
//   all blocks : combine the 32 stats partials (fixed order), then evaluate
//                layer-1 closed form for 256 rows each -> g_hidden
//   last block : hidden stats (fixed-order tree) + layer-2 closed form -> out,
//                then resets the ticket for graph replay.
// ---------------------------------------------------------------------------
__global__ void __launch_bounds__(256) finale_kernel(const float* __restrict__ W1,
                                                     const float* __restrict__ W2,
                                                     float* __restrict__ out)
{
    const int tid = threadIdx.x;
    __shared__ float s_Zsum, s_zmin, s_zmax;
    __shared__ int   s_jlast;
    __shared__ int   s_last;

    if (tid == 0) {
        float sum = 0.f;
        unsigned mnk = 0xFFFFFFFFu;
        unsigned long long mx = 0ULL;
        #pragma unroll
        for (int i = 0; i < SB; ++i) {
            sum += g_psum[i];
            mnk  = min(mnk, g_pmin[i]);
            mx   = max(mx,  g_pmax[i]);
        }
        s_Zsum  = sum;
        s_zmin  = fdec(mnk);
        s_zmax  = fdec((unsigned)(mx >> 32));
        s_jlast = (int)(unsigned)mx;
    }
    __syncthreads();

    {
        const float Zsum = s_Zsum, zmin = s_zmin, zmax = s_zmax;
        const int   jlast = s_jlast;
        const int r = blockIdx.x * 256 + tid;        // 32*256 = 8192 rows
        const float Wsum = g_w1sum[r];
        const float tmp = Wsum * Zsum / (Wsum - 1.f);
        float result = INFINITY;

        if (Wsum > 1.f) {
            if (zmin <= tmp) {                        // first mismatch at i=0 -> k=n-1
                float Wc = Wsum - W1[(size_t)r * NIN + jlast];
                float Zc = Zsum - zmax;
                result = Wc * Zc / (Wc - 1.f);
            }                                         // else: no mismatch -> inf
        } else {
            // rare general path (never taken for this data): serial row scan
            int cnt = 0; float sle = 0.f, wle = 0.f, m = -INFINITY; int jm = -1;
            for (int j = 0; j < NIN; ++j) {
                float zj = g_z[j];
                if (zj <= tmp) {
                    cnt++; sle += zj; wle += W1[(size_t)r * NIN + j];
                    if (zj > m || (zj == m && j > jm)) { m = zj; jm = j; }
                }
            }
            if (cnt == NIN) {
            } else if (cnt == 0) {
                float Wc = Wsum - W1[(size_t)r * NIN + jlast];
                float Zc = Zsum - zmax;
                result = Wc * Zc / (Wc - 1.f);
            } else if (cnt - 1 != 0) {
                float Zc = sle - m;
                float Wc = wle - W1[(size_t)r * NIN + jm];
                result = Wc * Zc / (Wc - 1.f);
            }
        }
        g_hidden[r] = result;
    }

    // ---- ticket: last-arriving block runs layer-2 ----
    __syncthreads();
    if (tid == 0) {
        __threadfence();                                    // release g_hidden
        unsigned t = atomicAdd(&g_ticket, 1u);
        s_last = (t == FIN_BLOCKS - 1) ? 1 : 0;
        if (s_last) __threadfence();                        // acquire all g_hidden
    }
    __syncthreads();
    if (!s_last) return;

    // ---- hidden stats: 256 threads, fixed-order strided + tree (deterministic) ----
    __shared__ float shf[256], shn[256], shx[256];
    __shared__ int   shj[256];
    float sum = 0.f, mn = INFINITY, mx = -INFINITY;
    int jm = -1;
    #pragma unroll
    for (int i = 0; i < N_HID / 256; ++i) {
        const int j = tid + i * 256;
        float v = g_hidden[j];
        sum += v;
        mn = fminf(mn, v);
        if (v > mx || (v == mx && j > jm)) { mx = v; jm = j; }
    }
    shf[tid] = sum; shn[tid] = mn; shx[tid] = mx; shj[tid] = jm;
    __syncthreads();
    for (int o = 128; o > 0; o >>= 1) {
        if (tid < o) {
            shf[tid] += shf[tid + o];
            shn[tid]  = fminf(shn[tid], shn[tid + o]);
            float v2 = shx[tid + o]; int i2 = shj[tid + o];
            if (v2 > shx[tid] || (v2 == shx[tid] && i2 > shj[tid])) { shx[tid] = v2; shj[tid] = i2; }
        }
        __syncthreads();
    }
    const float Zsum = shf[0];
    const float zmin = shn[0];
    const float zmax = shx[0];
    const int   jlast = shj[0];

    // ---- layer-2 closed form: 4 rows per thread, independent loads ----
    #pragma unroll
    for (int r = tid; r < N_OUT; r += 256) {
        const float Wsum = g_w2sum[r];
        const float tmp = Wsum * Zsum / (Wsum - 1.f);
        float result = INFINITY;

        if (Wsum > 1.f) {
            if (zmin <= tmp) {
                float Wc = Wsum - W2[(size_t)r * NIN + jlast];
                float Zc = Zsum - zmax;
                result = Wc * Zc / (Wc - 1.f);
            }
        } else {
            // rare general path (never taken for this data): serial row scan
            int cnt = 0; float sle = 0.f, wle = 0.f, m = -INFINITY; int jmm = -1;
            for (int j = 0; j < NIN; ++j) {
                float zj = g_hidden[j];
                if (zj <= tmp) {
                    cnt++; sle += zj; wle += W2[(size_t)r * NIN + j];
                    if (zj > m || (zj == m && j > jmm)) { m = zj; jmm = j; }
                }
            }
            if (cnt == NIN) {
            } else if (cnt == 0) {
                float Wc = Wsum - W2[(size_t)r * NIN + jlast];
                float Zc = Zsum - zmax;
                result = Wc * Zc / (Wc - 1.f);
            } else if (cnt - 1 != 0) {
                float Zc = sle - m;
                float Wc = wle - W2[(size_t)r * NIN + jmm];
                result = Wc * Zc / (Wc - 1.f);
            }
        }
        out[r] = result;
    }

    if (tid == 0) g_ticket = 0;   // reset for next graph replay (deterministic)
}

extern "C" void kernel_launch(void* const* d_in, const int* in_sizes, int n_in,
                              void* d_out, int out_size)
{
    const float* x  = (const float*)d_in[0];
    const float* W1 = (const float*)d_in[1];
    const float* W2 = (const float*)d_in[2];
    float* out = (float*)d_out;

    big_kernel<<<TOTAL_BLOCKS, 256>>>(x, W1, W2);   // all row sums + tail stats
    finale_kernel<<<FIN_BLOCKS, 256>>>(W1, W2, out); // layer-1 + layer-2 closed forms
}

// round 8
// speedup vs baseline: 1.0429x; 1.0429x over previous
#include <cuda_runtime.h>
#include <math.h>

static constexpr int NIN   = 8192;
static constexpr int N_HID = 8192;
static constexpr int N_OUT = 1024;
static constexpr int SB    = 32;                          // stats blocks (tail)
static constexpr int ROW_BLOCKS   = N_HID + N_OUT;        // 9216
static constexpr int TOTAL_BLOCKS = ROW_BLOCKS + SB;      // 9248
static constexpr int FA_BLOCKS    = 32;                   // finaleA grid

// ---------------- scratch (no allocations allowed) ----------------
__device__ float g_z[NIN];
__device__ float g_hidden[N_HID];
__device__ float g_w1sum[N_HID];
__device__ float g_w2sum[N_OUT];

// x-stats partials (written by big_kernel tail blocks)
__device__ float              g_psum[SB];
__device__ unsigned int       g_pmin[SB];
__device__ unsigned long long g_pmax[SB];
// hidden-stats partials (written by finaleA blocks)
__device__ float              g_qsum[FA_BLOCKS];
__device__ unsigned int       g_qmin[FA_BLOCKS];
__device__ unsigned long long g_qmax[FA_BLOCKS];

__device__ __forceinline__ unsigned int fkey(float v) {
    unsigned u = __float_as_uint(v);
    return (u & 0x80000000u) ? ~u : (u | 0x80000000u);
}
__device__ __forceinline__ float fdec(unsigned int k) {
    unsigned u = (k & 0x80000000u) ? (k ^ 0x80000000u) : ~k;
    return __uint_as_float(u);
}

// ---------------------------------------------------------------------------
// big_kernel — IDENTICAL to R7 (measured ~39us, 7.4 TB/s). Do not touch.
//   bids [0, 9216)   : W row sums (pure stream)
//   bids [9216, 9248): z = exp(x) + x-stats partials (free tail wave)
// ---------------------------------------------------------------------------
__global__ void __launch_bounds__(256) big_kernel(const float* __restrict__ x,
                                                  const float* __restrict__ W1,
                                                  const float* __restrict__ W2)
{
    const int bid = blockIdx.x;
    const int tid = threadIdx.x;

    if (bid >= ROW_BLOCKS) {
        const int sb = bid - ROW_BLOCKS;
        const int j  = sb * 256 + tid;
        const float v = expf(x[j]);
        g_z[j] = v;

        __shared__ float              ss[256];
        __shared__ unsigned int       smn[256];
        __shared__ unsigned long long smx[256];
        ss[tid]  = v;
        const unsigned k = fkey(v);
        smn[tid] = k;
        smx[tid] = ((unsigned long long)k << 32) | (unsigned)j;
        __syncthreads();
        for (int o = 128; o > 0; o >>= 1) {
            if (tid < o) {
                ss[tid]  += ss[tid + o];
                smn[tid]  = min(smn[tid], smn[tid + o]);
                smx[tid]  = max(smx[tid], smx[tid + o]);
            }
            __syncthreads();
        }
        if (tid == 0) {
            g_psum[sb] = ss[0];
            g_pmin[sb] = smn[0];
            g_pmax[sb] = smx[0];
        }
        return;
    }

    const bool isW2 = (bid >= N_HID);
    const float* __restrict__ W = isW2 ? W2 : W1;
    const int  row  = isW2 ? (bid - N_HID) : bid;
    const float4* __restrict__ Wr =
        reinterpret_cast<const float4*>(W + (size_t)row * NIN);

    float acc = 0.f;
    #pragma unroll
    for (int i = 0; i < NIN / 4 / 256; ++i) {
        float4 v = __ldcs(Wr + tid + i * 256);
        acc += (v.x + v.y) + (v.z + v.w);
    }
    #pragma unroll
    for (int o = 16; o > 0; o >>= 1) acc += __shfl_down_sync(0xffffffffu, acc, o);

    __shared__ float swp[8];
    const int wid = tid >> 5, lane = tid & 31;
    if (lane == 0) swp[wid] = acc;
    __syncthreads();

    if (tid == 0) {
        float Wsum = 0.f;
        #pragma unroll
        for (int w = 0; w < 8; ++w) Wsum += swp[w];
        if (isW2) g_w2sum[row] = Wsum; else g_w1sum[row] = Wsum;
    }
}

// ---------------------------------------------------------------------------
// finaleA (grid 32 x 256), no cross-block sync:
//   1) warp 0 combines the 32 x-stats partials (shuffle tree, fixed order)
//   2) each thread: layer-1 closed form for one row -> g_hidden
//   3) block-reduce the 256 fresh results -> hidden-stats partial
// ---------------------------------------------------------------------------
__global__ void __launch_bounds__(256) finaleA_kernel(const float* __restrict__ W1)
{
    const int tid = threadIdx.x;
    __shared__ float s_Zsum, s_zmin, s_zmax;
    __shared__ int   s_jlast;

    if (tid < 32) {
        float sum = g_psum[tid];
        unsigned mnk = g_pmin[tid];
        unsigned long long mx = g_pmax[tid];
        #pragma unroll
        for (int o = 16; o > 0; o >>= 1) {
            sum += __shfl_down_sync(0xffffffffu, sum, o);
            mnk  = min(mnk, __shfl_down_sync(0xffffffffu, mnk, o));
            mx   = max(mx,  __shfl_down_sync(0xffffffffu, mx,  o));
        }
        if (tid == 0) {
            s_Zsum  = sum;
            s_zmin  = fdec(mnk);
            s_zmax  = fdec((unsigned)(mx >> 32));
            s_jlast = (int)(unsigned)mx;
        }
    }
    __syncthreads();

    const float Zsum = s_Zsum, zmin = s_zmin, zmax = s_zmax;
    const int   jlast = s_jlast;
    const int   r = blockIdx.x * 256 + tid;
    const float Wsum = g_w1sum[r];
    const float tmp = Wsum * Zsum / (Wsum - 1.f);
    float result = INFINITY;

    if (Wsum > 1.f) {
        if (zmin <= tmp) {                        // first mismatch at i=0 -> k=n-1
            float Wc = Wsum - W1[(size_t)r * NIN + jlast];
            float Zc = Zsum - zmax;
            result = Wc * Zc / (Wc - 1.f);
        }                                         // else: no mismatch -> inf
    } else {
        // rare general path (never taken for this data): serial row scan
        int cnt = 0; float sle = 0.f, wle = 0.f, m = -INFINITY; int jm = -1;
        for (int j = 0; j < NIN; ++j) {
            float zj = g_z[j];
            if (zj <= tmp) {
                cnt++; sle += zj; wle += W1[(size_t)r * NIN + j];
                if (zj > m || (zj == m && j > jm)) { m = zj; jm = j; }
            }
        }
        if (cnt == NIN) {
        } else if (cnt == 0) {
            float Wc = Wsum - W1[(size_t)r * NIN + jlast];
            float Zc = Zsum - zmax;
            result = Wc * Zc / (Wc - 1.f);
        } else if (cnt - 1 != 0) {
            float Zc = sle - m;
            float Wc = wle - W1[(size_t)r * NIN + jm];
            result = Wc * Zc / (Wc - 1.f);
        }
    }
    g_hidden[r] = result;

    // ---- reduce this block's 256 results to a hidden-stats partial ----
    __shared__ float              hs[256];
    __shared__ unsigned int       hn[256];
    __shared__ unsigned long long hx[256];
    hs[tid] = result;
    const unsigned hk = fkey(result);
    hn[tid] = hk;
    hx[tid] = ((unsigned long long)hk << 32) | (unsigned)r;
    __syncthreads();
    for (int o = 128; o > 0; o >>= 1) {
        if (tid < o) {
            hs[tid] += hs[tid + o];
            hn[tid]  = min(hn[tid], hn[tid + o]);
            hx[tid]  = max(hx[tid], hx[tid + o]);
        }
        __syncthreads();
    }
    if (tid == 0) {
        g_qsum[blockIdx.x] = hs[0];
        g_qmin[blockIdx.x] = hn[0];
        g_qmax[blockIdx.x] = hx[0];
    }
}

// ---------------------------------------------------------------------------
// finaleB (1 block x 256): combine 32 hidden partials (one warp, fixed order),
// then layer-2 closed form: 4 rows per thread, independent scattered loads.
// ---------------------------------------------------------------------------
__global__ void __launch_bounds__(256) finaleB_kernel(const float* __restrict__ W2,
                                                      float* __restrict__ out)
{
    const int tid = threadIdx.x;
    __shared__ float s_Zsum, s_zmin, s_zmax;
    __shared__ int   s_jlast;

    if (tid < 32) {
        float sum = g_qsum[tid];
        unsigned mnk = g_qmin[tid];
        unsigned long long mx = g_qmax[tid];
        #pragma unroll
        for (int o = 16; o > 0; o >>= 1) {
            sum += __shfl_down_sync(0xffffffffu, sum, o);
            mnk  = min(mnk, __shfl_down_sync(0xffffffffu, mnk, o));
            mx   = max(mx,  __shfl_down_sync(0xffffffffu, mx,  o));
        }
        if (tid == 0) {
            s_Zsum  = sum;
            s_zmin  = fdec(mnk);
            s_zmax  = fdec((unsigned)(mx >> 32));
            s_jlast = (int)(unsigned)mx;
        }
    }
    __syncthreads();

    const float Zsum = s_Zsum, zmin = s_zmin, zmax = s_zmax;
    const int   jlast = s_jlast;

    #pragma unroll
    for (int r = tid; r < N_OUT; r += 256) {
        const float Wsum = g_w2sum[r];
        const float tmp = Wsum * Zsum / (Wsum - 1.f);
        float result = INFINITY;

        if (Wsum > 1.f) {
            if (zmin <= tmp) {
                float Wc = Wsum - W2[(size_t)r * NIN + jlast];
                float Zc = Zsum - zmax;
                result = Wc * Zc / (Wc - 1.f);
            }
        } else {
            // rare general path (never taken for this data): serial row scan
            int cnt = 0; float sle = 0.f, wle = 0.f, m = -INFINITY; int jmm = -1;
            for (int j = 0; j < NIN; ++j) {
                float zj = g_hidden[j];
                if (zj <= tmp) {
                    cnt++; sle += zj; wle += W2[(size_t)r * NIN + j];
                    if (zj > m || (zj == m && j > jmm)) { m = zj; jmm = j; }
                }
            }
            if (cnt == NIN) {
            } else if (cnt == 0) {
                float Wc = Wsum - W2[(size_t)r * NIN + jlast];
                float Zc = Zsum - zmax;
                result = Wc * Zc / (Wc - 1.f);
            } else if (cnt - 1 != 0) {
                float Zc = sle - m;
                float Wc = wle - W2[(size_t)r * NIN + jmm];
                result = Wc * Zc / (Wc - 1.f);
            }
        }
        out[r] = result;
    }
}

extern "C" void kernel_launch(void* const* d_in, const int* in_sizes, int n_in,
                              void* d_out, int out_size)
{
    const float* x  = (const float*)d_in[0];
    const float* W1 = (const float*)d_in[1];
    const float* W2 = (const float*)d_in[2];
    float* out = (float*)d_out;

    big_kernel<<<TOTAL_BLOCKS, 256>>>(x, W1, W2);     // stream + tail stats
    finaleA_kernel<<<FA_BLOCKS, 256>>>(W1);           // layer-1 + hidden partials
    finaleB_kernel<<<1, 256>>>(W2, out);              // combine + layer-2
}